// round 2
// baseline (speedup 1.0000x reference)
#include <cuda_runtime.h>
#include <math.h>

#define TOKENS 4096
#define H 1024
#define IDIM 4096
#define NE 8
#define MAXROWS 9216   // 8192 assignments + worst-case 128-row padding per expert

// ---------------- scratch (static device globals; no runtime allocation) ----
__device__ float g_xhat[(size_t)TOKENS * H];        // 16.8 MB
__device__ float g_h[(size_t)MAXROWS * IDIM];       // 151 MB
__device__ float g_eo[(size_t)MAXROWS * H];         // 37.7 MB
__device__ int   g_cnt[NE];
__device__ int   g_tok[NE * TOKENS];                // token id per (expert, slot)
__device__ int   g_pbase[NE + 1];                   // 128-aligned expert bases
__device__ int   g_te[TOKENS * 2];
__device__ int   g_ts[TOKENS * 2];
__device__ float g_tw[TOKENS * 2];

// ---------------- packed f32x2 helpers (sm_103a FFMA2) ----------------------
__device__ __forceinline__ unsigned long long pk2(float a, float b) {
    unsigned long long r;
    asm("mov.b64 %0, {%1, %2};" : "=l"(r) : "f"(a), "f"(b));
    return r;
}
__device__ __forceinline__ void upk2(unsigned long long v, float& a, float& b) {
    asm("mov.b64 {%0, %1}, %2;" : "=f"(a), "=f"(b) : "l"(v));
}
__device__ __forceinline__ void ffma2(unsigned long long& d, unsigned long long a,
                                      unsigned long long b) {
    asm("fma.rn.f32x2 %0, %1, %2, %0;" : "+l"(d) : "l"(a), "l"(b));
}

// ---------------- kernels ---------------------------------------------------
__global__ void zero_counts_kernel() {
    if (threadIdx.x < NE) g_cnt[threadIdx.x] = 0;
}

__global__ void routing_kernel(const float* __restrict__ x,
                               const float* __restrict__ rlw,
                               const float* __restrict__ rlb,
                               const float* __restrict__ rw,
                               const float* __restrict__ rb) {
    int t = blockIdx.x;
    int tid = threadIdx.x;
    __shared__ float xs[H];
    __shared__ float red[8], red2[8];
    __shared__ float logits[NE];
    __shared__ float s_mu, s_rs;

    const float* xrow = x + (size_t)t * H;
    float s = 0.f, s2 = 0.f;
    for (int k = tid; k < H; k += 256) {
        float v = xrow[k];
        xs[k] = v;
        s += v; s2 += v * v;
    }
    for (int o = 16; o; o >>= 1) {
        s  += __shfl_down_sync(~0u, s, o);
        s2 += __shfl_down_sync(~0u, s2, o);
    }
    int w = tid >> 5, l = tid & 31;
    if (l == 0) { red[w] = s; red2[w] = s2; }
    __syncthreads();
    if (tid == 0) {
        float a = 0.f, b = 0.f;
        for (int i = 0; i < 8; i++) { a += red[i]; b += red2[i]; }
        float mu = a * (1.0f / H);
        float var = b * (1.0f / H) - mu * mu;
        s_mu = mu;
        s_rs = rsqrtf(var + 1e-5f);
    }
    __syncthreads();
    float mu = s_mu, rs = s_rs;
    for (int k = tid; k < H; k += 256) {
        float xh = (xs[k] - mu) * rs;
        xs[k] = xh;
        g_xhat[(size_t)t * H + k] = xh;
    }
    __syncthreads();
    // warp-per-expert router dot
    if (w < NE) {
        float acc = 0.f;
        for (int k = l; k < H; k += 32) {
            float xln = xs[k] * rlw[k] + rlb[k];
            acc += xln * rw[k * NE + w];
        }
        for (int o = 16; o; o >>= 1) acc += __shfl_down_sync(~0u, acc, o);
        if (l == 0) logits[w] = acc + rb[w];
    }
    __syncthreads();
    if (tid == 0) {
        float v0 = -1e30f, v1 = -1e30f;
        int e0 = 0, e1 = 0;
        for (int e = 0; e < NE; e++) {
            float v = logits[e];
            if (v > v0)      { v1 = v0; e1 = e0; v0 = v; e0 = e; }
            else if (v > v1) { v1 = v;  e1 = e; }
        }
        float tt = expf(v1 - v0);
        float inv = 1.0f / (1.0f + tt);
        float w0 = inv, w1v = tt * inv;
        int s0 = atomicAdd(&g_cnt[e0], 1);
        int s1 = atomicAdd(&g_cnt[e1], 1);
        g_tok[e0 * TOKENS + s0] = t;
        g_tok[e1 * TOKENS + s1] = t;
        g_te[2 * t] = e0;     g_ts[2 * t] = s0;     g_tw[2 * t] = w0;
        g_te[2 * t + 1] = e1; g_ts[2 * t + 1] = s1; g_tw[2 * t + 1] = w1v;
    }
}

__global__ void offsets_kernel() {
    int acc = 0;
    for (int e = 0; e < NE; e++) {
        g_pbase[e] = acc;
        acc += ((g_cnt[e] + 127) >> 7) << 7;
    }
    g_pbase[NE] = acc;
}

// GEMM1: h = gelu( (xhat*ln_w[e]+ln_b[e]) @ w1[e] + b1[e] )
__global__ void __launch_bounds__(256, 2)
gemm1_kernel(const float* __restrict__ w1, const float* __restrict__ b1,
             const float* __restrict__ elw, const float* __restrict__ elb) {
    __shared__ float As[8][132];   // padded vs 128 to dodge store conflicts
    __shared__ float Bs[8][128];
    __shared__ int   rowTok[128];
    __shared__ float s_lnw[H];
    __shared__ float s_lnb[H];

    int tileRow = blockIdx.y * 128;
    int e = 0;
#pragma unroll
    for (int i = 1; i < NE; i++)
        if (tileRow >= g_pbase[i]) e = i;
    if (tileRow >= g_pbase[NE]) return;
    int base = g_pbase[e], cnt = g_cnt[e];

    int tid = threadIdx.x;
    if (tid < 128) {
        int loc = tileRow + tid - base;
        rowTok[tid] = (loc < cnt) ? g_tok[e * TOKENS + loc] : -1;
    }
    for (int k = tid; k < H; k += 256) {
        s_lnw[k] = elw[e * H + k];
        s_lnb[k] = elb[e * H + k];
    }
    __syncthreads();

    int colBase = blockIdx.x * 128;
    const float* Bp = w1 + (size_t)e * H * IDIM + colBase;
    int tx = tid & 15, ty = tid >> 4;

    unsigned long long acc[8][4];
#pragma unroll
    for (int i = 0; i < 8; i++)
#pragma unroll
        for (int j = 0; j < 4; j++) acc[i][j] = 0ull;

    int arow = tid >> 1, aseg = (tid & 1) * 4;
    int tokA = rowTok[arow]; if (tokA < 0) tokA = 0;
    const float* Ap = g_xhat + (size_t)tokA * H + aseg;
    int bk = tid >> 5, bcol = (tid & 31) * 4;

    for (int kk = 0; kk < H; kk += 8) {
        float4 av = *(const float4*)(Ap + kk);
        float4 lw = *(const float4*)(s_lnw + kk + aseg);
        float4 lb = *(const float4*)(s_lnb + kk + aseg);
        As[aseg + 0][arow] = av.x * lw.x + lb.x;
        As[aseg + 1][arow] = av.y * lw.y + lb.y;
        As[aseg + 2][arow] = av.z * lw.z + lb.z;
        As[aseg + 3][arow] = av.w * lw.w + lb.w;
        *(float4*)&Bs[bk][bcol] =
            *(const float4*)(Bp + (size_t)(kk + bk) * IDIM + bcol);
        __syncthreads();
#pragma unroll
        for (int k = 0; k < 8; k++) {
            float4 a0 = *(const float4*)&As[k][ty * 8];
            float4 a1 = *(const float4*)&As[k][ty * 8 + 4];
            float4 b0 = *(const float4*)&Bs[k][tx * 4];
            float4 b1v = *(const float4*)&Bs[k][64 + tx * 4];
            unsigned long long bp0 = pk2(b0.x, b0.y), bp1 = pk2(b0.z, b0.w);
            unsigned long long bp2 = pk2(b1v.x, b1v.y), bp3 = pk2(b1v.z, b1v.w);
            float aa[8] = {a0.x, a0.y, a0.z, a0.w, a1.x, a1.y, a1.z, a1.w};
#pragma unroll
            for (int i = 0; i < 8; i++) {
                unsigned long long ap = pk2(aa[i], aa[i]);
                ffma2(acc[i][0], ap, bp0);
                ffma2(acc[i][1], ap, bp1);
                ffma2(acc[i][2], ap, bp2);
                ffma2(acc[i][3], ap, bp3);
            }
        }
        __syncthreads();
    }

    int c0 = colBase + tx * 4;
    int c1 = colBase + 64 + tx * 4;
#pragma unroll
    for (int i = 0; i < 8; i++) {
        int grow = tileRow + ty * 8 + i;
        if (grow - base >= cnt) continue;
        float v[8];
        upk2(acc[i][0], v[0], v[1]);
        upk2(acc[i][1], v[2], v[3]);
        upk2(acc[i][2], v[4], v[5]);
        upk2(acc[i][3], v[6], v[7]);
#pragma unroll
        for (int j = 0; j < 4; j++) {
            float hv = v[j] + b1[e * IDIM + c0 + j];
            v[j] = 0.5f * hv * (1.0f + erff(hv * 0.70710678118654752f));
        }
#pragma unroll
        for (int j = 0; j < 4; j++) {
            float hv = v[4 + j] + b1[e * IDIM + c1 + j];
            v[4 + j] = 0.5f * hv * (1.0f + erff(hv * 0.70710678118654752f));
        }
        float* outp = g_h + (size_t)grow * IDIM;
        *(float4*)(outp + c0) = make_float4(v[0], v[1], v[2], v[3]);
        *(float4*)(outp + c1) = make_float4(v[4], v[5], v[6], v[7]);
    }
}

// GEMM2: eo = h @ w2[e] + b2[e]
__global__ void __launch_bounds__(256, 2)
gemm2_kernel(const float* __restrict__ w2, const float* __restrict__ b2) {
    __shared__ float As[8][132];
    __shared__ float Bs[8][128];

    int tileRow = blockIdx.y * 128;
    int e = 0;
#pragma unroll
    for (int i = 1; i < NE; i++)
        if (tileRow >= g_pbase[i]) e = i;
    if (tileRow >= g_pbase[NE]) return;
    int base = g_pbase[e], cnt = g_cnt[e];

    int tid = threadIdx.x;
    int tx = tid & 15, ty = tid >> 4;
    int colBase = blockIdx.x * 128;
    const float* Bp = w2 + (size_t)e * IDIM * H + colBase;

    unsigned long long acc[8][4];
#pragma unroll
    for (int i = 0; i < 8; i++)
#pragma unroll
        for (int j = 0; j < 4; j++) acc[i][j] = 0ull;

    int arow = tid >> 1, aseg = (tid & 1) * 4;
    const float* Ap = g_h + (size_t)(tileRow + arow) * IDIM + aseg;
    int bk = tid >> 5, bcol = (tid & 31) * 4;

    for (int kk = 0; kk < IDIM; kk += 8) {
        float4 av = *(const float4*)(Ap + kk);
        As[aseg + 0][arow] = av.x;
        As[aseg + 1][arow] = av.y;
        As[aseg + 2][arow] = av.z;
        As[aseg + 3][arow] = av.w;
        *(float4*)&Bs[bk][bcol] =
            *(const float4*)(Bp + (size_t)(kk + bk) * H + bcol);
        __syncthreads();
#pragma unroll
        for (int k = 0; k < 8; k++) {
            float4 a0 = *(const float4*)&As[k][ty * 8];
            float4 a1 = *(const float4*)&As[k][ty * 8 + 4];
            float4 b0 = *(const float4*)&Bs[k][tx * 4];
            float4 b1v = *(const float4*)&Bs[k][64 + tx * 4];
            unsigned long long bp0 = pk2(b0.x, b0.y), bp1 = pk2(b0.z, b0.w);
            unsigned long long bp2 = pk2(b1v.x, b1v.y), bp3 = pk2(b1v.z, b1v.w);
            float aa[8] = {a0.x, a0.y, a0.z, a0.w, a1.x, a1.y, a1.z, a1.w};
#pragma unroll
            for (int i = 0; i < 8; i++) {
                unsigned long long ap = pk2(aa[i], aa[i]);
                ffma2(acc[i][0], ap, bp0);
                ffma2(acc[i][1], ap, bp1);
                ffma2(acc[i][2], ap, bp2);
                ffma2(acc[i][3], ap, bp3);
            }
        }
        __syncthreads();
    }

    int c0 = colBase + tx * 4;
    int c1 = colBase + 64 + tx * 4;
#pragma unroll
    for (int i = 0; i < 8; i++) {
        int grow = tileRow + ty * 8 + i;
        if (grow - base >= cnt) continue;
        float v[8];
        upk2(acc[i][0], v[0], v[1]);
        upk2(acc[i][1], v[2], v[3]);
        upk2(acc[i][2], v[4], v[5]);
        upk2(acc[i][3], v[6], v[7]);
        float* outp = g_eo + (size_t)grow * H;
        *(float4*)(outp + c0) = make_float4(v[0] + b2[e * H + c0 + 0],
                                            v[1] + b2[e * H + c0 + 1],
                                            v[2] + b2[e * H + c0 + 2],
                                            v[3] + b2[e * H + c0 + 3]);
        *(float4*)(outp + c1) = make_float4(v[4] + b2[e * H + c1 + 0],
                                            v[5] + b2[e * H + c1 + 1],
                                            v[6] + b2[e * H + c1 + 2],
                                            v[7] + b2[e * H + c1 + 3]);
    }
}

__global__ void finalize_kernel(const float* __restrict__ olw,
                                const float* __restrict__ olb,
                                float* __restrict__ out) {
    int t = blockIdx.x;
    int tid = threadIdx.x;
    __shared__ float cs[H];
    __shared__ float red[8], red2[8];
    __shared__ float s_mu, s_rs;

    int e0 = g_te[2 * t], e1 = g_te[2 * t + 1];
    int a0 = g_pbase[e0] + g_ts[2 * t];
    int a1 = g_pbase[e1] + g_ts[2 * t + 1];
    float w0 = g_tw[2 * t], w1v = g_tw[2 * t + 1];
    const float* r0 = g_eo + (size_t)a0 * H;
    const float* r1 = g_eo + (size_t)a1 * H;

    float s = 0.f, s2 = 0.f;
    for (int k = tid; k < H; k += 256) {
        float v = w0 * r0[k] + w1v * r1[k];
        cs[k] = v;
        s += v; s2 += v * v;
    }
    for (int o = 16; o; o >>= 1) {
        s  += __shfl_down_sync(~0u, s, o);
        s2 += __shfl_down_sync(~0u, s2, o);
    }
    int w = tid >> 5, l = tid & 31;
    if (l == 0) { red[w] = s; red2[w] = s2; }
    __syncthreads();
    if (tid == 0) {
        float a = 0.f, b = 0.f;
        for (int i = 0; i < 8; i++) { a += red[i]; b += red2[i]; }
        float mu = a * (1.0f / H);
        float var = b * (1.0f / H) - mu * mu;
        s_mu = mu;
        s_rs = rsqrtf(var + 1e-5f);
    }
    __syncthreads();
    float mu = s_mu, rs = s_rs;
    for (int k = tid; k < H; k += 256) {
        out[(size_t)t * H + k] = (cs[k] - mu) * rs * olw[k] + olb[k];
    }
}

// ---------------- launch ----------------------------------------------------
extern "C" void kernel_launch(void* const* d_in, const int* in_sizes, int n_in,
                              void* d_out, int out_size) {
    const float* x   = (const float*)d_in[0];
    const float* rlw = (const float*)d_in[1];
    const float* rlb = (const float*)d_in[2];
    const float* rw  = (const float*)d_in[3];
    const float* rb  = (const float*)d_in[4];
    const float* elw = (const float*)d_in[5];
    const float* elb = (const float*)d_in[6];
    const float* w1  = (const float*)d_in[7];
    const float* b1  = (const float*)d_in[8];
    const float* w2  = (const float*)d_in[9];
    const float* b2  = (const float*)d_in[10];
    const float* olw = (const float*)d_in[11];
    const float* olb = (const float*)d_in[12];
    float* out = (float*)d_out;

    zero_counts_kernel<<<1, 32>>>();
    routing_kernel<<<TOKENS, 256>>>(x, rlw, rlb, rw, rb);
    offsets_kernel<<<1, 1>>>();
    gemm1_kernel<<<dim3(IDIM / 128, MAXROWS / 128), 256>>>(w1, b1, elw, elb);
    gemm2_kernel<<<dim3(H / 128, MAXROWS / 128), 256>>>(w2, b2);
    finalize_kernel<<<TOKENS, 256>>>(olw, olb, out);
}

// round 4
// speedup vs baseline: 1.3086x; 1.3086x over previous
#include <cuda_runtime.h>
#include <math.h>
#include <stdint.h>

#define TOKENS 4096
#define H 1024
#define IDIM 4096
#define NE 8
#define MAXROWS 9216   // 8192 assignments + worst-case 128-row padding per expert

// ---------------- scratch (static device globals; no runtime allocation) ----
__device__ float g_xhat[(size_t)TOKENS * H];        // 16.8 MB
__device__ float g_a[(size_t)MAXROWS * H];          // 37.7 MB  gathered+LN'd A (tf32)
__device__ float g_h[(size_t)MAXROWS * IDIM];       // 151 MB   gelu output (tf32)
__device__ float g_eo[(size_t)MAXROWS * H];         // 37.7 MB  expert output fp32
__device__ int   g_cnt[NE];
__device__ int   g_tok[NE * TOKENS];
__device__ int   g_pbase[NE + 1];
__device__ int   g_te[TOKENS * 2];
__device__ int   g_ts[TOKENS * 2];
__device__ float g_tw[TOKENS * 2];

// ---------------- PTX helpers ----------------------------------------------
__device__ __forceinline__ float to_tf32(float x) {
    float r;
    asm("cvt.rna.tf32.f32 %0, %1;" : "=f"(r) : "f"(x));
    return r;
}
__device__ __forceinline__ void cpa16(uint32_t dst, const void* src) {
    asm volatile("cp.async.cg.shared.global [%0], [%1], 16;" :: "r"(dst), "l"(src));
}
__device__ __forceinline__ void cpa_wait_all() {
    asm volatile("cp.async.wait_all;" ::: "memory");
}
__device__ __forceinline__ void mma_tf32(float* d, const uint32_t* a,
                                         uint32_t b0, uint32_t b1) {
    asm volatile(
        "mma.sync.aligned.m16n8k8.row.col.f32.tf32.tf32.f32 "
        "{%0,%1,%2,%3},{%4,%5,%6,%7},{%8,%9},{%0,%1,%2,%3};"
        : "+f"(d[0]), "+f"(d[1]), "+f"(d[2]), "+f"(d[3])
        : "r"(a[0]), "r"(a[1]), "r"(a[2]), "r"(a[3]), "r"(b0), "r"(b1));
}

// ---------------- routing ----------------------------------------------------
__global__ void zero_counts_kernel() {
    if (threadIdx.x < NE) g_cnt[threadIdx.x] = 0;
}

__global__ void routing_kernel(const float* __restrict__ x,
                               const float* __restrict__ rlw,
                               const float* __restrict__ rlb,
                               const float* __restrict__ rw,
                               const float* __restrict__ rb) {
    int t = blockIdx.x;
    int tid = threadIdx.x;
    __shared__ float xs[H];
    __shared__ float red[8], red2[8];
    __shared__ float logits[NE];
    __shared__ float s_mu, s_rs;

    const float* xrow = x + (size_t)t * H;
    float s = 0.f, s2 = 0.f;
    for (int k = tid; k < H; k += 256) {
        float v = xrow[k];
        xs[k] = v;
        s += v; s2 += v * v;
    }
    for (int o = 16; o; o >>= 1) {
        s  += __shfl_down_sync(~0u, s, o);
        s2 += __shfl_down_sync(~0u, s2, o);
    }
    int w = tid >> 5, l = tid & 31;
    if (l == 0) { red[w] = s; red2[w] = s2; }
    __syncthreads();
    if (tid == 0) {
        float a = 0.f, b = 0.f;
        for (int i = 0; i < 8; i++) { a += red[i]; b += red2[i]; }
        float mu = a * (1.0f / H);
        float var = b * (1.0f / H) - mu * mu;
        s_mu = mu;
        s_rs = rsqrtf(var + 1e-5f);
    }
    __syncthreads();
    float mu = s_mu, rs = s_rs;
    for (int k = tid; k < H; k += 256) {
        float xh = (xs[k] - mu) * rs;
        xs[k] = xh;
        g_xhat[(size_t)t * H + k] = xh;
    }
    __syncthreads();
    if (w < NE) {
        float acc = 0.f;
        for (int k = l; k < H; k += 32) {
            float xln = xs[k] * rlw[k] + rlb[k];
            acc += xln * rw[k * NE + w];
        }
        for (int o = 16; o; o >>= 1) acc += __shfl_down_sync(~0u, acc, o);
        if (l == 0) logits[w] = acc + rb[w];
    }
    __syncthreads();
    if (tid == 0) {
        float v0 = -1e30f, v1 = -1e30f;
        int e0 = 0, e1 = 0;
        for (int e = 0; e < NE; e++) {
            float v = logits[e];
            if (v > v0)      { v1 = v0; e1 = e0; v0 = v; e0 = e; }
            else if (v > v1) { v1 = v;  e1 = e; }
        }
        float tt = expf(v1 - v0);
        float inv = 1.0f / (1.0f + tt);
        int s0 = atomicAdd(&g_cnt[e0], 1);
        int s1 = atomicAdd(&g_cnt[e1], 1);
        g_tok[e0 * TOKENS + s0] = t;
        g_tok[e1 * TOKENS + s1] = t;
        g_te[2 * t] = e0;     g_ts[2 * t] = s0;     g_tw[2 * t] = inv;
        g_te[2 * t + 1] = e1; g_ts[2 * t + 1] = s1; g_tw[2 * t + 1] = tt * inv;
    }
}

__global__ void offsets_kernel() {
    int acc = 0;
    for (int e = 0; e < NE; e++) {
        g_pbase[e] = acc;
        acc += ((g_cnt[e] + 127) >> 7) << 7;
    }
    g_pbase[NE] = acc;
}

// Gather + expert-LN affine + tf32 round into g_a
__global__ void prep_a_kernel(const float* __restrict__ elw,
                              const float* __restrict__ elb) {
    int a = blockIdx.x;
    int t = a >> 1, j = a & 1;
    int e = g_te[2 * t + j];
    int slot = g_ts[2 * t + j];
    int row = g_pbase[e] + slot;
    const float* src = g_xhat + (size_t)t * H;
    const float* lw = elw + (size_t)e * H;
    const float* lb = elb + (size_t)e * H;
    float* dst = g_a + (size_t)row * H;
    for (int k = threadIdx.x; k < H; k += 256)
        dst[k] = to_tf32(src[k] * lw[k] + lb[k]);
}

// ---------------- grouped GEMM via mma.sync tf32 ----------------------------
// Block tile 128x128, BK=32, double buffered. 8 warps = 4(M) x 2(N).
// As: [2][128][36] floats, Bs: [2][32][132] floats.
#define AS_STRIDE 36
#define BS_STRIDE 132
#define AS_STAGE (128 * AS_STRIDE)
#define BS_STAGE (32 * BS_STRIDE)
#define SMEM_DYN ((2 * AS_STAGE + 2 * BS_STAGE) * 4)

// MODE 0: GEMM1 A=g_a (K=1024), B=w1[e] [K][IDIM], out=g_h (bias+gelu+tf32)
// MODE 1: GEMM2 A=g_h (K=4096), B=w2[e] [K][H],    out=g_eo (bias)
template <int MODE>
__global__ void __launch_bounds__(256, 2)
gemm_mma_kernel(const float* __restrict__ Bmat, const float* __restrict__ bias) {
    extern __shared__ float sm[];
    float* As = sm;
    float* Bs = sm + 2 * AS_STAGE;

    int tileRow = blockIdx.y * 128;
    int e = 0;
#pragma unroll
    for (int i = 1; i < NE; i++)
        if (tileRow >= g_pbase[i]) e = i;
    if (tileRow >= g_pbase[NE]) return;
    int bbase = g_pbase[e], cnt = g_cnt[e];

    const int K  = (MODE == 0) ? H : IDIM;
    const int NO = (MODE == 0) ? IDIM : H;
    const float* Asrc = ((MODE == 0) ? g_a : g_h) + (size_t)tileRow * K;
    float* Out = (MODE == 0) ? g_h : g_eo;
    int colBase = blockIdx.x * 128;
    const float* Bsrc = Bmat + (size_t)e * ((size_t)H * IDIM) + colBase;

    int tid = threadIdx.x;
    int lane = tid & 31, warp = tid >> 5;
    int wm = (warp & 3) * 32;      // warp M offset
    int wn = (warp >> 2) * 64;     // warp N offset
    int g = lane >> 2, tg = lane & 3;

    // A cp.async mapping: 2 threads/row, 16 floats each (4 x 16B)
    int am = tid >> 1;
    int ao = (tid & 1) * 16;
    uint32_t asBase = (uint32_t)__cvta_generic_to_shared(As) + (am * AS_STRIDE + ao) * 4;
    const float* aGlob = Asrc + (size_t)am * K + ao;

    // B mapping: 8 threads/row(k), 16 floats each
    int bk = tid >> 3;
    int bo = (tid & 7) * 16;
    const float* bGlob = Bsrc + (size_t)bk * NO + bo;
    float* bsBase = Bs + bk * BS_STRIDE + bo;

    float acc[2][8][4];
#pragma unroll
    for (int mi = 0; mi < 2; mi++)
#pragma unroll
        for (int ni = 0; ni < 8; ni++)
#pragma unroll
            for (int q = 0; q < 4; q++) acc[mi][ni][q] = 0.f;

    const int NC = K / 32;
    float br[16];

    // prologue: fill stage 0
#pragma unroll
    for (int j = 0; j < 4; j++)
        cpa16(asBase + j * 16, aGlob + j * 4);
#pragma unroll
    for (int j = 0; j < 16; j++) br[j] = bGlob[(j >> 2) * 0 + (j & 3) + (j >> 2) * 4];
    // (the expression above is just bGlob[j]; keep simple)
#pragma unroll
    for (int j = 0; j < 16; j++) br[j] = bGlob[j];
#pragma unroll
    for (int j = 0; j < 16; j++) bsBase[j] = to_tf32(br[j]);
    cpa_wait_all();
    __syncthreads();

    for (int c = 0; c < NC; c++) {
        int p = c & 1;
        int pn = p ^ 1;
        if (c + 1 < NC) {
            int kk = (c + 1) * 32;
            uint32_t ad = asBase + pn * AS_STAGE * 4;
#pragma unroll
            for (int j = 0; j < 4; j++)
                cpa16(ad + j * 16, aGlob + kk + j * 4);
            const float* bg = bGlob + (size_t)kk * NO;
#pragma unroll
            for (int j = 0; j < 16; j++) br[j] = bg[j];
        }

        const float* Ap = As + p * AS_STAGE;
        const float* Bp = Bs + p * BS_STAGE;
#pragma unroll
        for (int ks = 0; ks < 4; ks++) {
            int kq = ks * 8;
            uint32_t afr[2][4];
#pragma unroll
            for (int mi = 0; mi < 2; mi++) {
                int m0 = wm + mi * 16 + g;
                afr[mi][0] = __float_as_uint(Ap[(m0)     * AS_STRIDE + kq + tg]);
                afr[mi][1] = __float_as_uint(Ap[(m0 + 8) * AS_STRIDE + kq + tg]);
                afr[mi][2] = __float_as_uint(Ap[(m0)     * AS_STRIDE + kq + tg + 4]);
                afr[mi][3] = __float_as_uint(Ap[(m0 + 8) * AS_STRIDE + kq + tg + 4]);
            }
#pragma unroll
            for (int ni = 0; ni < 8; ni++) {
                uint32_t b0 = __float_as_uint(Bp[(kq + tg)     * BS_STRIDE + wn + ni * 8 + g]);
                uint32_t b1 = __float_as_uint(Bp[(kq + tg + 4) * BS_STRIDE + wn + ni * 8 + g]);
                mma_tf32(acc[0][ni], afr[0], b0, b1);
                mma_tf32(acc[1][ni], afr[1], b0, b1);
            }
        }

        if (c + 1 < NC) {
            float* bd = Bs + pn * BS_STAGE + bk * BS_STRIDE + bo;
#pragma unroll
            for (int j = 0; j < 16; j++) bd[j] = to_tf32(br[j]);
        }
        cpa_wait_all();
        __syncthreads();
    }

    // epilogue
#pragma unroll
    for (int mi = 0; mi < 2; mi++) {
        int r0 = tileRow + wm + mi * 16 + g;
        int r1 = r0 + 8;
        bool live0 = (r0 - bbase) < cnt;
        bool live1 = (r1 - bbase) < cnt;
#pragma unroll
        for (int ni = 0; ni < 8; ni++) {
            int gc = colBase + wn + ni * 8 + 2 * tg;
            float bv0 = bias[(size_t)e * NO + gc];
            float bv1 = bias[(size_t)e * NO + gc + 1];
            float v0 = acc[mi][ni][0] + bv0;
            float v1 = acc[mi][ni][1] + bv1;
            float v2 = acc[mi][ni][2] + bv0;
            float v3 = acc[mi][ni][3] + bv1;
            if (MODE == 0) {
                v0 = to_tf32(0.5f * v0 * (1.0f + erff(v0 * 0.70710678118654752f)));
                v1 = to_tf32(0.5f * v1 * (1.0f + erff(v1 * 0.70710678118654752f)));
                v2 = to_tf32(0.5f * v2 * (1.0f + erff(v2 * 0.70710678118654752f)));
                v3 = to_tf32(0.5f * v3 * (1.0f + erff(v3 * 0.70710678118654752f)));
            }
            if (live0) *(float2*)(Out + (size_t)r0 * NO + gc) = make_float2(v0, v1);
            if (live1) *(float2*)(Out + (size_t)r1 * NO + gc) = make_float2(v2, v3);
        }
    }
}

// ---------------- finalize ---------------------------------------------------
__global__ void finalize_kernel(const float* __restrict__ olw,
                                const float* __restrict__ olb,
                                float* __restrict__ out) {
    int t = blockIdx.x;
    int tid = threadIdx.x;
    __shared__ float cs[H];
    __shared__ float red[8], red2[8];
    __shared__ float s_mu, s_rs;

    int e0 = g_te[2 * t], e1 = g_te[2 * t + 1];
    int a0 = g_pbase[e0] + g_ts[2 * t];
    int a1 = g_pbase[e1] + g_ts[2 * t + 1];
    float w0 = g_tw[2 * t], w1v = g_tw[2 * t + 1];
    const float* r0 = g_eo + (size_t)a0 * H;
    const float* r1 = g_eo + (size_t)a1 * H;

    float s = 0.f, s2 = 0.f;
    for (int k = tid; k < H; k += 256) {
        float v = w0 * r0[k] + w1v * r1[k];
        cs[k] = v;
        s += v; s2 += v * v;
    }
    for (int o = 16; o; o >>= 1) {
        s  += __shfl_down_sync(~0u, s, o);
        s2 += __shfl_down_sync(~0u, s2, o);
    }
    int w = tid >> 5, l = tid & 31;
    if (l == 0) { red[w] = s; red2[w] = s2; }
    __syncthreads();
    if (tid == 0) {
        float a = 0.f, b = 0.f;
        for (int i = 0; i < 8; i++) { a += red[i]; b += red2[i]; }
        float mu = a * (1.0f / H);
        float var = b * (1.0f / H) - mu * mu;
        s_mu = mu;
        s_rs = rsqrtf(var + 1e-5f);
    }
    __syncthreads();
    float mu = s_mu, rs = s_rs;
    for (int k = tid; k < H; k += 256) {
        out[(size_t)t * H + k] = (cs[k] - mu) * rs * olw[k] + olb[k];
    }
}

// ---------------- launch -----------------------------------------------------
extern "C" void kernel_launch(void* const* d_in, const int* in_sizes, int n_in,
                              void* d_out, int out_size) {
    const float* x   = (const float*)d_in[0];
    const float* rlw = (const float*)d_in[1];
    const float* rlb = (const float*)d_in[2];
    const float* rw  = (const float*)d_in[3];
    const float* rb  = (const float*)d_in[4];
    const float* elw = (const float*)d_in[5];
    const float* elb = (const float*)d_in[6];
    const float* w1  = (const float*)d_in[7];
    const float* b1  = (const float*)d_in[8];
    const float* w2  = (const float*)d_in[9];
    const float* b2  = (const float*)d_in[10];
    const float* olw = (const float*)d_in[11];
    const float* olb = (const float*)d_in[12];
    float* out = (float*)d_out;

    static int attr_set = 0;
    if (!attr_set) {
        cudaFuncSetAttribute(gemm_mma_kernel<0>,
                             cudaFuncAttributeMaxDynamicSharedMemorySize, SMEM_DYN);
        cudaFuncSetAttribute(gemm_mma_kernel<1>,
                             cudaFuncAttributeMaxDynamicSharedMemorySize, SMEM_DYN);
        attr_set = 1;
    }

    zero_counts_kernel<<<1, 32>>>();
    routing_kernel<<<TOKENS, 256>>>(x, rlw, rlb, rw, rb);
    offsets_kernel<<<1, 1>>>();
    prep_a_kernel<<<2 * TOKENS, 256>>>(elw, elb);
    gemm_mma_kernel<0><<<dim3(IDIM / 128, MAXROWS / 128), 256, SMEM_DYN>>>(w1, b1);
    gemm_mma_kernel<1><<<dim3(H / 128, MAXROWS / 128), 256, SMEM_DYN>>>(w2, b2);
    finalize_kernel<<<TOKENS, 256>>>(olw, olb, out);
}

// round 6
// speedup vs baseline: 2.4003x; 1.8343x over previous
#include <cuda_runtime.h>
#include <math.h>
#include <stdint.h>

#define TOKENS 4096
#define H 1024
#define IDIM 4096
#define NE 8
#define MAXROWS 9216   // 8192 assignments + worst-case 128-row padding per expert

// ---------------- scratch (static device globals; no runtime allocation) ----
__device__ float g_xhat[(size_t)TOKENS * H];        // 16.8 MB
__device__ float g_a[(size_t)MAXROWS * H];          // 37.7 MB  A for GEMM1 (tf32, K-perm)
__device__ float g_h[(size_t)MAXROWS * IDIM];       // 151 MB   gelu out (tf32, K-perm)
__device__ float g_eo[(size_t)MAXROWS * H];         // 37.7 MB  expert output fp32
__device__ float g_w1r[(size_t)NE * H * IDIM];      // 128 MB   w1 tf32, N-perm
__device__ float g_w2r[(size_t)NE * H * IDIM];      // 128 MB   w2 tf32, N-perm
__device__ int   g_cnt[NE];
__device__ int   g_tok[NE * TOKENS];
__device__ int   g_pbase[NE + 1];
__device__ int   g_te[TOKENS * 2];
__device__ int   g_ts[TOKENS * 2];
__device__ float g_tw[TOKENS * 2];

// ---------------- PTX helpers ----------------------------------------------
__device__ __forceinline__ float to_tf32(float x) {
    float r;
    asm("cvt.rna.tf32.f32 %0, %1;" : "=f"(r) : "f"(x));
    return r;
}
__device__ __forceinline__ void cpa16(uint32_t dst, const void* src) {
    asm volatile("cp.async.cg.shared.global [%0], [%1], 16;" :: "r"(dst), "l"(src));
}
__device__ __forceinline__ void cpa_commit() {
    asm volatile("cp.async.commit_group;" ::: "memory");
}
__device__ __forceinline__ void cpa_wait1() {
    asm volatile("cp.async.wait_group 1;" ::: "memory");
}
__device__ __forceinline__ void mma_tf32(float* d, uint32_t a0, uint32_t a1,
                                         uint32_t a2, uint32_t a3,
                                         float b0f, float b1f) {
    uint32_t b0 = __float_as_uint(b0f), b1 = __float_as_uint(b1f);
    asm volatile(
        "mma.sync.aligned.m16n8k8.row.col.f32.tf32.tf32.f32 "
        "{%0,%1,%2,%3},{%4,%5,%6,%7},{%8,%9},{%0,%1,%2,%3};"
        : "+f"(d[0]), "+f"(d[1]), "+f"(d[2]), "+f"(d[3])
        : "r"(a0), "r"(a1), "r"(a2), "r"(a3), "r"(b0), "r"(b1));
}

// A K-dim permutation within each 32-float block: pos = (k&3)*8 + (k&31)/4
__device__ __forceinline__ int perm_a(int k) {
    return (k & ~31) | ((k & 3) << 3) | ((k & 31) >> 2);
}
// B N-dim permutation within each 128-float block
__device__ __forceinline__ int perm_b(int n) {
    return (n & ~127) | (n & 64) | (((n >> 3) & 4) << 3) | ((n & 7) << 2)
         | ((n >> 3) & 3);
}

// ---------------- routing ----------------------------------------------------
__global__ void zero_counts_kernel() {
    if (threadIdx.x < NE) g_cnt[threadIdx.x] = 0;
}

__global__ void routing_kernel(const float* __restrict__ x,
                               const float* __restrict__ rlw,
                               const float* __restrict__ rlb,
                               const float* __restrict__ rw,
                               const float* __restrict__ rb) {
    int t = blockIdx.x;
    int tid = threadIdx.x;
    __shared__ float xs[H];
    __shared__ float red[8], red2[8];
    __shared__ float logits[NE];
    __shared__ float s_mu, s_rs;

    const float* xrow = x + (size_t)t * H;
    float s = 0.f, s2 = 0.f;
    for (int k = tid; k < H; k += 256) {
        float v = xrow[k];
        xs[k] = v;
        s += v; s2 += v * v;
    }
    for (int o = 16; o; o >>= 1) {
        s  += __shfl_down_sync(~0u, s, o);
        s2 += __shfl_down_sync(~0u, s2, o);
    }
    int w = tid >> 5, l = tid & 31;
    if (l == 0) { red[w] = s; red2[w] = s2; }
    __syncthreads();
    if (tid == 0) {
        float a = 0.f, b = 0.f;
        for (int i = 0; i < 8; i++) { a += red[i]; b += red2[i]; }
        float mu = a * (1.0f / H);
        float var = b * (1.0f / H) - mu * mu;
        s_mu = mu;
        s_rs = rsqrtf(var + 1e-5f);
    }
    __syncthreads();
    float mu = s_mu, rs = s_rs;
    for (int k = tid; k < H; k += 256) {
        float xh = (xs[k] - mu) * rs;
        xs[k] = xh;
        g_xhat[(size_t)t * H + k] = xh;
    }
    __syncthreads();
    if (w < NE) {
        float acc = 0.f;
        for (int k = l; k < H; k += 32) {
            float xln = xs[k] * rlw[k] + rlb[k];
            acc += xln * rw[k * NE + w];
        }
        for (int o = 16; o; o >>= 1) acc += __shfl_down_sync(~0u, acc, o);
        if (l == 0) logits[w] = acc + rb[w];
    }
    __syncthreads();
    if (tid == 0) {
        float v0 = -1e30f, v1 = -1e30f;
        int e0 = 0, e1 = 0;
        for (int e = 0; e < NE; e++) {
            float v = logits[e];
            if (v > v0)      { v1 = v0; e1 = e0; v0 = v; e0 = e; }
            else if (v > v1) { v1 = v;  e1 = e; }
        }
        float tt = expf(v1 - v0);
        float inv = 1.0f / (1.0f + tt);
        int s0 = atomicAdd(&g_cnt[e0], 1);
        int s1 = atomicAdd(&g_cnt[e1], 1);
        g_tok[e0 * TOKENS + s0] = t;
        g_tok[e1 * TOKENS + s1] = t;
        g_te[2 * t] = e0;     g_ts[2 * t] = s0;     g_tw[2 * t] = inv;
        g_te[2 * t + 1] = e1; g_ts[2 * t + 1] = s1; g_tw[2 * t + 1] = tt * inv;
    }
}

__global__ void offsets_kernel() {
    int acc = 0;
    for (int e = 0; e < NE; e++) {
        g_pbase[e] = acc;
        acc += ((g_cnt[e] + 127) >> 7) << 7;
    }
    g_pbase[NE] = acc;
}

// Gather + expert-LN affine + tf32 round + K-perm into g_a
__global__ void prep_a_kernel(const float* __restrict__ elw,
                              const float* __restrict__ elb) {
    int a = blockIdx.x;
    int t = a >> 1, j = a & 1;
    int e = g_te[2 * t + j];
    int slot = g_ts[2 * t + j];
    int row = g_pbase[e] + slot;
    const float* src = g_xhat + (size_t)t * H;
    const float* lw = elw + (size_t)e * H;
    const float* lb = elb + (size_t)e * H;
    float* dst = g_a + (size_t)row * H;
    for (int k = threadIdx.x; k < H; k += 256)
        dst[perm_a(k)] = to_tf32(src[k] * lw[k] + lb[k]);
}

// Round weights to tf32 + permute N within 128-blocks
__global__ void prep_w_kernel(const float* __restrict__ src,
                              float* __restrict__ dst, int N) {
    size_t row = blockIdx.y;
    int n0 = blockIdx.x * 1024 + threadIdx.x * 4;
    float4 v = *(const float4*)(src + row * N + n0);
    float* d = dst + row * N;
    float vv[4] = {v.x, v.y, v.z, v.w};
#pragma unroll
    for (int j = 0; j < 4; j++)
        d[perm_b(n0 + j)] = to_tf32(vv[j]);
}

// ---------------- grouped GEMM via mma.sync tf32 ----------------------------
// Block tile 128x128, BK=32, cp.async double-buffered. 8 warps = 4(M) x 2(N).
#define ASS 36
#define BSS 136
#define ASTAGE (128 * ASS)
#define BSTAGE (32 * BSS)
#define SMEM_DYN ((2 * ASTAGE + 2 * BSTAGE) * 4)

// MODE 0: GEMM1 A=g_a (K=1024), B=g_w1r, out=g_h (bias+gelu+tf32, K-perm)
// MODE 1: GEMM2 A=g_h (K=4096), B=g_w2r, out=g_eo (bias)
template <int MODE>
__global__ void __launch_bounds__(256, 2)
gemm_mma_kernel(const float* __restrict__ bias) {
    extern __shared__ float sm[];
    float* As = sm;
    float* Bs = sm + 2 * ASTAGE;

    int tileRow = blockIdx.y * 128;
    int e = 0;
#pragma unroll
    for (int i = 1; i < NE; i++)
        if (tileRow >= g_pbase[i]) e = i;
    if (tileRow >= g_pbase[NE]) return;
    int bbase = g_pbase[e], cnt = g_cnt[e];

    const int K  = (MODE == 0) ? H : IDIM;
    const int NO = (MODE == 0) ? IDIM : H;
    const float* Asrc = ((MODE == 0) ? g_a : g_h) + (size_t)tileRow * K;
    float* Out = (MODE == 0) ? g_h : g_eo;
    int colBase = blockIdx.x * 128;
    const float* Bsrc = ((MODE == 0) ? g_w1r : g_w2r)
                      + (size_t)e * ((size_t)H * IDIM) + colBase;

    int tid = threadIdx.x;
    int lane = tid & 31, warp = tid >> 5;
    int wm = (warp & 3) * 32;
    int wn = (warp >> 2) * 64;
    int g = lane >> 2, tg = lane & 3;

    uint32_t asU = (uint32_t)__cvta_generic_to_shared(As);
    uint32_t bsU = (uint32_t)__cvta_generic_to_shared(Bs);

    // loader thread mappings
    int ar = tid >> 1;            // unused placeholder to keep regs low
    (void)ar;

    float acc[2][8][4];
#pragma unroll
    for (int mi = 0; mi < 2; mi++)
#pragma unroll
        for (int ni = 0; ni < 8; ni++)
#pragma unroll
            for (int q = 0; q < 4; q++) acc[mi][ni][q] = 0.f;

    const int NC = K / 32;

    // -- async stage loader: A tile 128x32, B tile 32x128 (both 16KB) --
    auto issue = [&](int buf, int c) {
        uint32_t ab = asU + buf * (ASTAGE * 4);
        const float* ag = Asrc + c * 32;
#pragma unroll
        for (int j = 0; j < 4; j++) {
            int q = tid + 256 * j;
            int r = q >> 3, o = q & 7;
            cpa16(ab + (uint32_t)(r * ASS + o * 4) * 4,
                  ag + (size_t)r * K + o * 4);
        }
        uint32_t bb = bsU + buf * (BSTAGE * 4);
        const float* bg = Bsrc + (size_t)(c * 32) * NO;
#pragma unroll
        for (int j = 0; j < 4; j++) {
            int q = tid + 256 * j;
            int r = q >> 5, o = q & 31;
            cpa16(bb + (uint32_t)(r * BSS + o * 4) * 4,
                  bg + (size_t)r * NO + o * 4);
        }
    };

    issue(0, 0); cpa_commit();
    if (NC > 1) issue(1, 1);
    cpa_commit();
    cpa_wait1();
    __syncthreads();

    for (int c = 0; c < NC; c++) {
        const float* Ap = As + (c & 1) * ASTAGE;
        const float* Bp = Bs + (c & 1) * BSTAGE;
#pragma unroll
        for (int kp = 0; kp < 2; kp++) {
            float4 a0v = *(const float4*)(Ap + (wm +      g) * ASS + tg * 8 + kp * 4);
            float4 a1v = *(const float4*)(Ap + (wm +  8 + g) * ASS + tg * 8 + kp * 4);
            float4 a2v = *(const float4*)(Ap + (wm + 16 + g) * ASS + tg * 8 + kp * 4);
            float4 a3v = *(const float4*)(Ap + (wm + 24 + g) * ASS + tg * 8 + kp * 4);
#pragma unroll
            for (int s = 0; s < 2; s++) {
                int kr = (kp * 2 + s) * 8 + tg;
                float4 q0 = *(const float4*)(Bp + kr * BSS + wn + 4 * g);
                float4 q1 = *(const float4*)(Bp + kr * BSS + wn + 4 * g + 32);
                float4 q2 = *(const float4*)(Bp + (kr + 4) * BSS + wn + 4 * g);
                float4 q3 = *(const float4*)(Bp + (kr + 4) * BSS + wn + 4 * g + 32);
                uint32_t af00, af01, af02, af03, af10, af11, af12, af13;
                if (s == 0) {
                    af00 = __float_as_uint(a0v.x); af01 = __float_as_uint(a1v.x);
                    af02 = __float_as_uint(a0v.y); af03 = __float_as_uint(a1v.y);
                    af10 = __float_as_uint(a2v.x); af11 = __float_as_uint(a3v.x);
                    af12 = __float_as_uint(a2v.y); af13 = __float_as_uint(a3v.y);
                } else {
                    af00 = __float_as_uint(a0v.z); af01 = __float_as_uint(a1v.z);
                    af02 = __float_as_uint(a0v.w); af03 = __float_as_uint(a1v.w);
                    af10 = __float_as_uint(a2v.z); af11 = __float_as_uint(a3v.z);
                    af12 = __float_as_uint(a2v.w); af13 = __float_as_uint(a3v.w);
                }
                float b0a[8] = {q0.x, q0.y, q0.z, q0.w, q1.x, q1.y, q1.z, q1.w};
                float b1a[8] = {q2.x, q2.y, q2.z, q2.w, q3.x, q3.y, q3.z, q3.w};
#pragma unroll
                for (int ni = 0; ni < 8; ni++) {
                    mma_tf32(acc[0][ni], af00, af01, af02, af03, b0a[ni], b1a[ni]);
                    mma_tf32(acc[1][ni], af10, af11, af12, af13, b0a[ni], b1a[ni]);
                }
            }
        }
        __syncthreads();
        if (c + 2 < NC) issue(c & 1, c + 2);
        cpa_commit();
        cpa_wait1();
        __syncthreads();
    }

    // ---------------- epilogue ----------------
#pragma unroll
    for (int mi = 0; mi < 2; mi++) {
        int r0 = tileRow + wm + mi * 16 + g;
        int r1 = r0 + 8;
        bool live0 = (r0 - bbase) < cnt;
        bool live1 = (r1 - bbase) < cnt;
#pragma unroll
        for (int ni = 0; ni < 8; ni++) {
            int gc = colBase + wn + ni * 8 + 2 * tg;
            float bv0 = bias[(size_t)e * NO + gc];
            float bv1 = bias[(size_t)e * NO + gc + 1];
            float v0 = acc[mi][ni][0] + bv0;
            float v1 = acc[mi][ni][1] + bv1;
            float v2 = acc[mi][ni][2] + bv0;
            float v3 = acc[mi][ni][3] + bv1;
            if (MODE == 0) {
                // bias + exact gelu + tf32-round, store K-permuted for GEMM2
                v0 = to_tf32(0.5f * v0 * (1.0f + erff(v0 * 0.70710678118654752f)));
                v1 = to_tf32(0.5f * v1 * (1.0f + erff(v1 * 0.70710678118654752f)));
                v2 = to_tf32(0.5f * v2 * (1.0f + erff(v2 * 0.70710678118654752f)));
                v3 = to_tf32(0.5f * v3 * (1.0f + erff(v3 * 0.70710678118654752f)));
                int i0 = perm_a(gc);
                int i1 = perm_a(gc + 1);
                if (live0) { Out[(size_t)r0 * NO + i0] = v0; Out[(size_t)r0 * NO + i1] = v1; }
                if (live1) { Out[(size_t)r1 * NO + i0] = v2; Out[(size_t)r1 * NO + i1] = v3; }
            } else {
                if (live0) *(float2*)(Out + (size_t)r0 * NO + gc) = make_float2(v0, v1);
                if (live1) *(float2*)(Out + (size_t)r1 * NO + gc) = make_float2(v2, v3);
            }
        }
    }
}

// ---------------- finalize ---------------------------------------------------
__global__ void finalize_kernel(const float* __restrict__ olw,
                                const float* __restrict__ olb,
                                float* __restrict__ out) {
    int t = blockIdx.x;
    int tid = threadIdx.x;
    __shared__ float cs[H];
    __shared__ float red[8], red2[8];
    __shared__ float s_mu, s_rs;

    int e0 = g_te[2 * t], e1 = g_te[2 * t + 1];
    int a0 = g_pbase[e0] + g_ts[2 * t];
    int a1 = g_pbase[e1] + g_ts[2 * t + 1];
    float w0 = g_tw[2 * t], w1v = g_tw[2 * t + 1];
    const float* r0 = g_eo + (size_t)a0 * H;
    const float* r1 = g_eo + (size_t)a1 * H;

    float s = 0.f, s2 = 0.f;
    for (int k = tid; k < H; k += 256) {
        float v = w0 * r0[k] + w1v * r1[k];
        cs[k] = v;
        s += v; s2 += v * v;
    }
    for (int o = 16; o; o >>= 1) {
        s  += __shfl_down_sync(~0u, s, o);
        s2 += __shfl_down_sync(~0u, s2, o);
    }
    int w = tid >> 5, l = tid & 31;
    if (l == 0) { red[w] = s; red2[w] = s2; }
    __syncthreads();
    if (tid == 0) {
        float a = 0.f, b = 0.f;
        for (int i = 0; i < 8; i++) { a += red[i]; b += red2[i]; }
        float mu = a * (1.0f / H);
        float var = b * (1.0f / H) - mu * mu;
        s_mu = mu;
        s_rs = rsqrtf(var + 1e-5f);
    }
    __syncthreads();
    float mu = s_mu, rs = s_rs;
    for (int k = tid; k < H; k += 256) {
        out[(size_t)t * H + k] = (cs[k] - mu) * rs * olw[k] + olb[k];
    }
}

// ---------------- launch -----------------------------------------------------
extern "C" void kernel_launch(void* const* d_in, const int* in_sizes, int n_in,
                              void* d_out, int out_size) {
    const float* x   = (const float*)d_in[0];
    const float* rlw = (const float*)d_in[1];
    const float* rlb = (const float*)d_in[2];
    const float* rw  = (const float*)d_in[3];
    const float* rb  = (const float*)d_in[4];
    const float* elw = (const float*)d_in[5];
    const float* elb = (const float*)d_in[6];
    const float* w1  = (const float*)d_in[7];
    const float* b1  = (const float*)d_in[8];
    const float* w2  = (const float*)d_in[9];
    const float* b2  = (const float*)d_in[10];
    const float* olw = (const float*)d_in[11];
    const float* olb = (const float*)d_in[12];
    float* out = (float*)d_out;

    static int attr_set = 0;
    if (!attr_set) {
        cudaFuncSetAttribute(gemm_mma_kernel<0>,
                             cudaFuncAttributeMaxDynamicSharedMemorySize, SMEM_DYN);
        cudaFuncSetAttribute(gemm_mma_kernel<1>,
                             cudaFuncAttributeMaxDynamicSharedMemorySize, SMEM_DYN);
        attr_set = 1;
    }

    float* w1r; cudaGetSymbolAddress((void**)&w1r, g_w1r);
    float* w2r; cudaGetSymbolAddress((void**)&w2r, g_w2r);

    zero_counts_kernel<<<1, 32>>>();
    routing_kernel<<<TOKENS, 256>>>(x, rlw, rlb, rw, rb);
    offsets_kernel<<<1, 1>>>();
    prep_a_kernel<<<2 * TOKENS, 256>>>(elw, elb);
    prep_w_kernel<<<dim3(IDIM / 1024, NE * H), 256>>>(w1, w1r, IDIM);
    prep_w_kernel<<<dim3(H / 1024, NE * IDIM), 256>>>(w2, w2r, H);
    gemm_mma_kernel<0><<<dim3(IDIM / 128, MAXROWS / 128), 256, SMEM_DYN>>>(b1);
    gemm_mma_kernel<1><<<dim3(H / 128, MAXROWS / 128), 256, SMEM_DYN>>>(b2);
    finalize_kernel<<<TOKENS, 256>>>(olw, olb, out);
}